// round 6
// baseline (speedup 1.0000x reference)
#include <cuda_runtime.h>
#include <cstdint>
#include <math.h>

#define BB   64
#define NN   4096
#define DD   64
#define HH   256
#define SS   1024
#define TOT  49152   // 3 * D * H

// raw hypernet output (k1 -> k2)
__device__ float g_params[BB * (size_t)TOT];
// normalized tf32 weights in MMA-ready swizzled layout (k2 -> k3)
__device__ uint32_t g_wT[BB * (size_t)TOT];

// ======================= helpers =======================
__device__ __forceinline__ uint32_t f2tf(float f) {
    uint32_t r;
    asm("cvt.rna.tf32.f32 %0, %1;" : "=r"(r) : "f"(f));
    return r;
}
__device__ __forceinline__ float tanha(float x) {
    float y;
    asm("tanh.approx.f32 %0, %1;" : "=f"(y) : "f"(x));
    return y;
}
__device__ __forceinline__ uint32_t smem_u32(const void* p) {
    uint32_t a;
    asm("{ .reg .u64 t; cvta.to.shared.u64 t, %1; cvt.u32.u64 %0, t; }" : "=r"(a) : "l"(p));
    return a;
}
__device__ __forceinline__ void cpa16(uint32_t dst, const void* src) {
    asm volatile("cp.async.cg.shared.global [%0], [%1], 16;" :: "r"(dst), "l"(src));
}
#define CP_COMMIT() asm volatile("cp.async.commit_group;" ::: "memory")
#define CP_WAIT1()  asm volatile("cp.async.wait_group 1;" ::: "memory")

// D += A * B  (m16n8k8, tf32 inputs, fp32 accum)
__device__ __forceinline__ void mma_tf32(float* d, const uint32_t* a, uint32_t b0, uint32_t b1) {
    asm volatile("mma.sync.aligned.m16n8k8.row.col.f32.tf32.tf32.f32 "
                 "{%0,%1,%2,%3}, {%4,%5,%6,%7}, {%8,%9}, {%0,%1,%2,%3};"
                 : "+f"(d[0]), "+f"(d[1]), "+f"(d[2]), "+f"(d[3])
                 : "r"(a[0]), "r"(a[1]), "r"(a[2]), "r"(a[3]), "r"(b0), "r"(b1));
}

// ======================= kernel 1: hypernet GEMM via mma.sync tf32 =======================
#define K1_SMEM ((2 * 64 * 36 + 2 * 32 * 136) * 4)   // 53248 B

__global__ __launch_bounds__(256) void k1_mma(const float* __restrict__ s,
                                              const float* __restrict__ W,
                                              const float* __restrict__ bias) {
    extern __shared__ float sk[];
    float* sA = sk;              // 2 * 2304
    float* sB = sk + 4608;       // 2 * 4352
    const int n0  = blockIdx.x * 128;
    const int tid = threadIdx.x;
    const int w = tid >> 5, lane = tid & 31;
    const int r = lane >> 2, q = lane & 3;
    const int m0 = (w & 1) * 32, nw = (w >> 1) * 32;
    const uint32_t sbA = smem_u32(sA), sbB = smem_u32(sB);

    #define K1_LOAD(st, k0) do {                                                   \
        _Pragma("unroll")                                                          \
        for (int i = 0; i < 2; i++) {                                              \
            int c = tid + i * 256;                                                 \
            int row = c >> 3, cc = c & 7;                                          \
            cpa16(sbA + (uint32_t)((st) * 2304 + row * 36 + cc * 4) * 4,           \
                  s + (size_t)row * SS + (k0) + cc * 4);                           \
        }                                                                          \
        _Pragma("unroll")                                                          \
        for (int i = 0; i < 4; i++) {                                              \
            int c = tid + i * 256;                                                 \
            int row = c >> 5, cc = c & 31;                                         \
            cpa16(sbB + (uint32_t)((st) * 4352 + row * 136 + cc * 4) * 4,          \
                  W + (size_t)((k0) + row) * TOT + n0 + cc * 4);                   \
        }                                                                          \
    } while (0)

    float acc[2][4][4];
    #pragma unroll
    for (int mf = 0; mf < 2; mf++)
        #pragma unroll
        for (int nf = 0; nf < 4; nf++)
            acc[mf][nf][0] = acc[mf][nf][1] = acc[mf][nf][2] = acc[mf][nf][3] = 0.f;

    K1_LOAD(0, 0);  CP_COMMIT();
    K1_LOAD(1, 32); CP_COMMIT();

    for (int ks = 0; ks < 32; ks++) {
        CP_WAIT1();
        __syncthreads();
        const int st = ks & 1;
        const float* A  = sA + st * 2304;
        const float* Bp = sB + st * 4352;
        #pragma unroll
        for (int kk = 0; kk < 4; kk++) {
            uint32_t a[2][4];
            #pragma unroll
            for (int mf = 0; mf < 2; mf++) {
                const int mr = m0 + mf * 16 + r;
                a[mf][0] = __float_as_uint(A[mr * 36 + kk * 8 + q]);
                a[mf][1] = __float_as_uint(A[(mr + 8) * 36 + kk * 8 + q]);
                a[mf][2] = __float_as_uint(A[mr * 36 + kk * 8 + q + 4]);
                a[mf][3] = __float_as_uint(A[(mr + 8) * 36 + kk * 8 + q + 4]);
            }
            #pragma unroll
            for (int nf = 0; nf < 4; nf++) {
                const int cb = nw + nf * 8 + r;
                uint32_t b0 = __float_as_uint(Bp[(kk * 8 + q) * 136 + cb]);
                uint32_t b1 = __float_as_uint(Bp[(kk * 8 + q + 4) * 136 + cb]);
                mma_tf32(acc[0][nf], a[0], b0, b1);
                mma_tf32(acc[1][nf], a[1], b0, b1);
            }
        }
        __syncthreads();
        const int kn = (ks + 2) * 32;
        if (kn < SS) { K1_LOAD(st, kn); }
        CP_COMMIT();
    }

    #pragma unroll
    for (int nf = 0; nf < 4; nf++) {
        float2 bv = *(const float2*)(bias + n0 + nw + nf * 8 + 2 * q);
        #pragma unroll
        for (int mf = 0; mf < 2; mf++) {
            const int mr = m0 + mf * 16 + r;
            float* o0 = g_params + (size_t)mr * TOT + n0 + nw + nf * 8 + 2 * q;
            *(float2*)o0 = make_float2(acc[mf][nf][0] + bv.x, acc[mf][nf][1] + bv.y);
            float* o1 = g_params + (size_t)(mr + 8) * TOT + n0 + nw + nf * 8 + 2 * q;
            *(float2*)o1 = make_float2(acc[mf][nf][2] + bv.x, acc[mf][nf][3] + bv.y);
        }
    }
    #undef K1_LOAD
}

// ======================= kernel 2: normalize -> tf32 swizzled MMA layout =======================
// Wg/Wv stored: word(k=d, n=h) = m*16384 + d*256 + (h ^ ((d&3)<<3))
// fc2   stored: word(k=h, n=d) = 32768  + h*64  + (d ^ ((h&3)<<3))
__global__ __launch_bounds__(256) void k2_normalize() {
    __shared__ float sinv[256];
    __shared__ float part[4][64];
    const int b = blockIdx.x, tid = threadIdx.x;
    const float* P = g_params + (size_t)b * TOT;
    uint32_t* dst = g_wT + (size_t)b * TOT;

    #pragma unroll
    for (int m = 0; m < 2; m++) {
        const float* src = P + m * 16384;
        {
            float ss = 0.f;
            #pragma unroll 8
            for (int d = 0; d < 64; d++) { float v = src[d * 256 + tid]; ss += v * v; }
            sinv[tid] = 1.f / fmaxf(sqrtf(ss), 1e-12f);
        }
        __syncthreads();
        for (int idx = tid; idx < 16384; idx += 256) {
            int d = idx >> 8, h = idx & 255;
            float v = src[idx] * sinv[h];
            dst[m * 16384 + d * 256 + (h ^ ((d & 3) << 3))] = f2tf(v);
        }
        __syncthreads();
    }
    {
        const float* src = P + 32768;
        int q = tid >> 6, dd = tid & 63;
        float ss = 0.f;
        #pragma unroll 8
        for (int h = q * 64; h < q * 64 + 64; h++) { float v = src[h * 64 + dd]; ss += v * v; }
        part[q][dd] = ss;
        __syncthreads();
        if (tid < 64)
            sinv[tid] = 1.f / fmaxf(sqrtf(part[0][tid] + part[1][tid] + part[2][tid] + part[3][tid]), 1e-12f);
        __syncthreads();
        for (int idx = tid; idx < 16384; idx += 256) {
            int h = idx >> 6, d = idx & 63;
            float v = src[idx] * sinv[d];
            dst[32768 + h * 64 + (d ^ ((h & 3) << 3))] = f2tf(v);
        }
    }
}

// ======================= kernel 3: mma.sync tf32 fused MLP, 16 warps =======================
// grid (8, 64): 512 rows per CTA, 8 groups of 64 rows.
// 16 warps: mw = w&3 -> 16-row m-tile; hq = w>>2 -> 64-col H quarter.
// smem: 49152 words weights + 8704 words scratch (xn/out buffers [64][68] x2).
#define K3_SMEM ((49152 + 8704) * 4)   // 231424 B

__global__ __launch_bounds__(512, 1) void k3_main(const float* __restrict__ x,
                                                  const float* __restrict__ scale,
                                                  float* __restrict__ out) {
    extern __shared__ uint32_t su[];
    float* sc = (float*)(su + 49152);        // scratch: [64][68] x 2
    const int tid = threadIdx.x, w = tid >> 5, lane = tid & 31;
    const int b = blockIdx.y;
    const int hq = w >> 2, mw = w & 3, m0 = mw * 16;
    const int r = lane >> 2, q = lane & 3, q8 = q << 3;
    const int nq0 = hq * 64;
    const bool qodd = (q & 1);
    const int srcA = (r << 2) + (q >> 1);

    // preload weights (already tf32 + swizzled)
    {
        const float4* wsrc = (const float4*)(g_wT + (size_t)b * TOT);
        float4* wdst = (float4*)su;
        #pragma unroll 4
        for (int i = tid; i < 12288; i += 512) wdst[i] = wsrc[i];
    }
    const int srow = tid >> 3, sqc = (tid & 7) * 8;
    const float4 scA = *(const float4*)(scale + sqc);
    const float4 scB = *(const float4*)(scale + sqc + 4);
    __syncthreads();

    const uint32_t* Wg = su;
    const uint32_t* Wv = su + 16384;
    const uint32_t* Wf = su + 32768;

    for (int g = 0; g < 8; g++) {
        const int row0 = blockIdx.x * 512 + g * 64;

        // ---- stage RMSNorm'd xn (tf32 RNE) into sc[0..4352); keep residual in regs ----
        float4 xv0, xv1;
        {
            const float4* xr = (const float4*)(x + ((size_t)b * NN + row0 + srow) * DD + sqc);
            xv0 = xr[0]; xv1 = xr[1];
            float ssq = xv0.x * xv0.x + xv0.y * xv0.y + xv0.z * xv0.z + xv0.w * xv0.w
                      + xv1.x * xv1.x + xv1.y * xv1.y + xv1.z * xv1.z + xv1.w * xv1.w;
            ssq += __shfl_xor_sync(0xffffffffu, ssq, 1);
            ssq += __shfl_xor_sync(0xffffffffu, ssq, 2);
            ssq += __shfl_xor_sync(0xffffffffu, ssq, 4);
            const float rr = rsqrtf(ssq * (1.0f / 64.0f) + 1e-6f);
            uint4 o0, o1;
            o0.x = f2tf(xv0.x * rr * scA.x); o0.y = f2tf(xv0.y * rr * scA.y);
            o0.z = f2tf(xv0.z * rr * scA.z); o0.w = f2tf(xv0.w * rr * scA.w);
            o1.x = f2tf(xv1.x * rr * scB.x); o1.y = f2tf(xv1.y * rr * scB.y);
            o1.z = f2tf(xv1.z * rr * scB.z); o1.w = f2tf(xv1.w * rr * scB.w);
            *(uint4*)&sc[srow * 68 + sqc]     = o0;
            *(uint4*)&sc[srow * 68 + sqc + 4] = o1;
        }
        __syncthreads();

        float oacc[8][4];
        #pragma unroll
        for (int i = 0; i < 8; i++) { oacc[i][0] = oacc[i][1] = oacc[i][2] = oacc[i][3] = 0.f; }

        #pragma unroll
        for (int ch = 0; ch < 2; ch++) {
            const int nb = nq0 + ch * 32;

            // ---- MMA1: gate/value [16 x 32] over k=64 ----
            float ga[4][4], va[4][4];
            #pragma unroll
            for (int i = 0; i < 4; i++) {
                ga[i][0] = ga[i][1] = ga[i][2] = ga[i][3] = 0.f;
                va[i][0] = va[i][1] = va[i][2] = va[i][3] = 0.f;
            }
            #pragma unroll
            for (int kt = 0; kt < 8; kt++) {
                uint32_t xa[4];
                xa[0] = __float_as_uint(sc[(m0 + r) * 68 + kt * 8 + q]);
                xa[1] = __float_as_uint(sc[(m0 + r + 8) * 68 + kt * 8 + q]);
                xa[2] = __float_as_uint(sc[(m0 + r) * 68 + kt * 8 + q + 4]);
                xa[3] = __float_as_uint(sc[(m0 + r + 8) * 68 + kt * 8 + q + 4]);
                const uint32_t* g0 = Wg + (kt * 8 + q) * 256;
                const uint32_t* v0 = Wv + (kt * 8 + q) * 256;
                #pragma unroll
                for (int nt = 0; nt < 4; nt++) {
                    const int c = ((nb + nt * 8) ^ q8) + r;
                    mma_tf32(ga[nt], xa, g0[c], g0[c + 1024]);
                    mma_tf32(va[nt], xa, v0[c], v0[c + 1024]);
                }
            }

            // ---- silu*value, shuffle-transpose acc->A layout, MMA2 accumulate ----
            #pragma unroll
            for (int nt = 0; nt < 4; nt++) {
                float h0 = 0.5f * ga[nt][0] * (1.f + tanha(0.5f * ga[nt][0])) * va[nt][0];
                float h1 = 0.5f * ga[nt][1] * (1.f + tanha(0.5f * ga[nt][1])) * va[nt][1];
                float h2 = 0.5f * ga[nt][2] * (1.f + tanha(0.5f * ga[nt][2])) * va[nt][2];
                float h3 = 0.5f * ga[nt][3] * (1.f + tanha(0.5f * ga[nt][3])) * va[nt][3];
                // owner of h(r, col): lane r*4 + col/2, element (col&1)
                float v0 = __shfl_sync(0xffffffffu, h0, srcA);
                float v1 = __shfl_sync(0xffffffffu, h1, srcA);
                float v2 = __shfl_sync(0xffffffffu, h2, srcA);
                float v3 = __shfl_sync(0xffffffffu, h3, srcA);
                float w0 = __shfl_sync(0xffffffffu, h0, srcA + 2);
                float w1 = __shfl_sync(0xffffffffu, h1, srcA + 2);
                float w2 = __shfl_sync(0xffffffffu, h2, srcA + 2);
                float w3 = __shfl_sync(0xffffffffu, h3, srcA + 2);
                uint32_t ha[4];
                ha[0] = f2tf(qodd ? v1 : v0);   // (r,   q)
                ha[1] = f2tf(qodd ? v3 : v2);   // (r+8, q)
                ha[2] = f2tf(qodd ? w1 : w0);   // (r,   q+4)
                ha[3] = f2tf(qodd ? w3 : w2);   // (r+8, q+4)
                const uint32_t* f0 = Wf + (nb + nt * 8 + q) * 64;
                #pragma unroll
                for (int dt = 0; dt < 8; dt++) {
                    const int c = ((dt * 8) ^ q8) + r;
                    mma_tf32(oacc[dt], ha, f0[c], f0[c + 256]);
                }
            }
        }
        __syncthreads();   // all xn reads done; scratch becomes out buffers

        // ---- two-round reduction across H quarters ----
        float* buf = sc + (hq & 1) * 4352;
        if (hq < 2) {
            #pragma unroll
            for (int dt = 0; dt < 8; dt++) {
                *(float2*)&buf[(m0 + r) * 68 + dt * 8 + 2 * q]     = make_float2(oacc[dt][0], oacc[dt][1]);
                *(float2*)&buf[(m0 + r + 8) * 68 + dt * 8 + 2 * q] = make_float2(oacc[dt][2], oacc[dt][3]);
            }
        }
        __syncthreads();
        if (hq >= 2) {
            #pragma unroll
            for (int dt = 0; dt < 8; dt++) {
                float2 p0 = *(float2*)&buf[(m0 + r) * 68 + dt * 8 + 2 * q];
                float2 p1 = *(float2*)&buf[(m0 + r + 8) * 68 + dt * 8 + 2 * q];
                p0.x += oacc[dt][0]; p0.y += oacc[dt][1];
                p1.x += oacc[dt][2]; p1.y += oacc[dt][3];
                *(float2*)&buf[(m0 + r) * 68 + dt * 8 + 2 * q]     = p0;
                *(float2*)&buf[(m0 + r + 8) * 68 + dt * 8 + 2 * q] = p1;
            }
        }
        __syncthreads();

        // ---- final: buf0 + buf1 + residual -> gmem ----
        {
            float4 a0 = *(float4*)&sc[srow * 68 + sqc];
            float4 a1 = *(float4*)&sc[srow * 68 + sqc + 4];
            float4 c0 = *(float4*)&sc[4352 + srow * 68 + sqc];
            float4 c1 = *(float4*)&sc[4352 + srow * 68 + sqc + 4];
            float* orow = out + ((size_t)b * NN + row0 + srow) * DD + sqc;
            *(float4*)orow       = make_float4(a0.x + c0.x + xv0.x, a0.y + c0.y + xv0.y,
                                               a0.z + c0.z + xv0.z, a0.w + c0.w + xv0.w);
            *(float4*)(orow + 4) = make_float4(a1.x + c1.x + xv1.x, a1.y + c1.y + xv1.y,
                                               a1.z + c1.z + xv1.z, a1.w + c1.w + xv1.w);
        }
        __syncthreads();
    }
}

// ======================= launch =======================
extern "C" void kernel_launch(void* const* d_in, const int* in_sizes, int n_in,
                              void* d_out, int out_size) {
    const float* x     = (const float*)d_in[0];
    const float* s     = (const float*)d_in[1];
    const float* W     = (const float*)d_in[2];
    const float* bias  = (const float*)d_in[3];
    const float* scale = (const float*)d_in[4];
    float* out = (float*)d_out;

    cudaFuncSetAttribute(k1_mma, cudaFuncAttributeMaxDynamicSharedMemorySize, K1_SMEM);
    k1_mma<<<dim3(TOT / 128), 256, K1_SMEM>>>(s, W, bias);

    k2_normalize<<<dim3(BB), 256>>>();

    cudaFuncSetAttribute(k3_main, cudaFuncAttributeMaxDynamicSharedMemorySize, K3_SMEM);
    k3_main<<<dim3(8, BB), 256 * 2, K3_SMEM>>>(x, scale, out);
}

// round 7
// speedup vs baseline: 1.5249x; 1.5249x over previous
#include <cuda_runtime.h>
#include <cuda_fp16.h>
#include <cstdint>
#include <math.h>

#define BB   64
#define NN   4096
#define DD   64
#define HH   256
#define SS   1024
#define TOT  49152   // 3 * D * H
#define WPB  24576   // half2 words per batch (3*D*H/2)

// raw hypernet output (k1 -> k2)
__device__ float g_params[BB * (size_t)TOT];
// normalized fp16 weights, half2-packed along k, XOR-swizzled (k2 -> k3)
__device__ uint32_t g_wT[BB * (size_t)WPB];

// ======================= helpers =======================
__device__ __forceinline__ float tanha(float x) {
    float y;
    asm("tanh.approx.f32 %0, %1;" : "=f"(y) : "f"(x));
    return y;
}
__device__ __forceinline__ uint32_t pack2(float lo, float hi) {
    __half2 h = __floats2half2_rn(lo, hi);
    return *(uint32_t*)&h;
}
__device__ __forceinline__ uint32_t smem_u32(const void* p) {
    uint32_t a;
    asm("{ .reg .u64 t; cvta.to.shared.u64 t, %1; cvt.u32.u64 %0, t; }" : "=r"(a) : "l"(p));
    return a;
}
__device__ __forceinline__ void cpa16(uint32_t dst, const void* src) {
    asm volatile("cp.async.cg.shared.global [%0], [%1], 16;" :: "r"(dst), "l"(src));
}
#define CP_COMMIT() asm volatile("cp.async.commit_group;" ::: "memory")
#define CP_WAIT1()  asm volatile("cp.async.wait_group 1;" ::: "memory")

// D += A * B  (m16n8k8, tf32 inputs, fp32 accum) — kernel 1
__device__ __forceinline__ void mma_tf32(float* d, const uint32_t* a, uint32_t b0, uint32_t b1) {
    asm volatile("mma.sync.aligned.m16n8k8.row.col.f32.tf32.tf32.f32 "
                 "{%0,%1,%2,%3}, {%4,%5,%6,%7}, {%8,%9}, {%0,%1,%2,%3};"
                 : "+f"(d[0]), "+f"(d[1]), "+f"(d[2]), "+f"(d[3])
                 : "r"(a[0]), "r"(a[1]), "r"(a[2]), "r"(a[3]), "r"(b0), "r"(b1));
}
// D += A * B  (m16n8k16, fp16 inputs, fp32 accum) — kernel 3
__device__ __forceinline__ void mma_f16(float* d, const uint32_t* a, uint32_t b0, uint32_t b1) {
    asm volatile("mma.sync.aligned.m16n8k16.row.col.f32.f16.f16.f32 "
                 "{%0,%1,%2,%3}, {%4,%5,%6,%7}, {%8,%9}, {%0,%1,%2,%3};"
                 : "+f"(d[0]), "+f"(d[1]), "+f"(d[2]), "+f"(d[3])
                 : "r"(a[0]), "r"(a[1]), "r"(a[2]), "r"(a[3]), "r"(b0), "r"(b1));
}

// ======================= kernel 1: hypernet GEMM via mma.sync tf32 (frozen) =======================
#define K1_SMEM ((2 * 64 * 36 + 2 * 32 * 136) * 4)   // 53248 B

__global__ __launch_bounds__(256) void k1_mma(const float* __restrict__ s,
                                              const float* __restrict__ W,
                                              const float* __restrict__ bias) {
    extern __shared__ float sk[];
    float* sA = sk;              // 2 * 2304
    float* sB = sk + 4608;       // 2 * 4352
    const int n0  = blockIdx.x * 128;
    const int tid = threadIdx.x;
    const int w = tid >> 5, lane = tid & 31;
    const int r = lane >> 2, q = lane & 3;
    const int m0 = (w & 1) * 32, nw = (w >> 1) * 32;
    const uint32_t sbA = smem_u32(sA), sbB = smem_u32(sB);

    #define K1_LOAD(st, k0) do {                                                   \
        _Pragma("unroll")                                                          \
        for (int i = 0; i < 2; i++) {                                              \
            int c = tid + i * 256;                                                 \
            int row = c >> 3, cc = c & 7;                                          \
            cpa16(sbA + (uint32_t)((st) * 2304 + row * 36 + cc * 4) * 4,           \
                  s + (size_t)row * SS + (k0) + cc * 4);                           \
        }                                                                          \
        _Pragma("unroll")                                                          \
        for (int i = 0; i < 4; i++) {                                              \
            int c = tid + i * 256;                                                 \
            int row = c >> 5, cc = c & 31;                                         \
            cpa16(sbB + (uint32_t)((st) * 4352 + row * 136 + cc * 4) * 4,          \
                  W + (size_t)((k0) + row) * TOT + n0 + cc * 4);                   \
        }                                                                          \
    } while (0)

    float acc[2][4][4];
    #pragma unroll
    for (int mf = 0; mf < 2; mf++)
        #pragma unroll
        for (int nf = 0; nf < 4; nf++)
            acc[mf][nf][0] = acc[mf][nf][1] = acc[mf][nf][2] = acc[mf][nf][3] = 0.f;

    K1_LOAD(0, 0);  CP_COMMIT();
    K1_LOAD(1, 32); CP_COMMIT();

    for (int ks = 0; ks < 32; ks++) {
        CP_WAIT1();
        __syncthreads();
        const int st = ks & 1;
        const float* A  = sA + st * 2304;
        const float* Bp = sB + st * 4352;
        #pragma unroll
        for (int kk = 0; kk < 4; kk++) {
            uint32_t a[2][4];
            #pragma unroll
            for (int mf = 0; mf < 2; mf++) {
                const int mr = m0 + mf * 16 + r;
                a[mf][0] = __float_as_uint(A[mr * 36 + kk * 8 + q]);
                a[mf][1] = __float_as_uint(A[(mr + 8) * 36 + kk * 8 + q]);
                a[mf][2] = __float_as_uint(A[mr * 36 + kk * 8 + q + 4]);
                a[mf][3] = __float_as_uint(A[(mr + 8) * 36 + kk * 8 + q + 4]);
            }
            #pragma unroll
            for (int nf = 0; nf < 4; nf++) {
                const int cb = nw + nf * 8 + r;
                uint32_t b0 = __float_as_uint(Bp[(kk * 8 + q) * 136 + cb]);
                uint32_t b1 = __float_as_uint(Bp[(kk * 8 + q + 4) * 136 + cb]);
                mma_tf32(acc[0][nf], a[0], b0, b1);
                mma_tf32(acc[1][nf], a[1], b0, b1);
            }
        }
        __syncthreads();
        const int kn = (ks + 2) * 32;
        if (kn < SS) { K1_LOAD(st, kn); }
        CP_COMMIT();
    }

    #pragma unroll
    for (int nf = 0; nf < 4; nf++) {
        float2 bv = *(const float2*)(bias + n0 + nw + nf * 8 + 2 * q);
        #pragma unroll
        for (int mf = 0; mf < 2; mf++) {
            const int mr = m0 + mf * 16 + r;
            float* o0 = g_params + (size_t)mr * TOT + n0 + nw + nf * 8 + 2 * q;
            *(float2*)o0 = make_float2(acc[mf][nf][0] + bv.x, acc[mf][nf][1] + bv.y);
            float* o1 = g_params + (size_t)(mr + 8) * TOT + n0 + nw + nf * 8 + 2 * q;
            *(float2*)o1 = make_float2(acc[mf][nf][2] + bv.x, acc[mf][nf][3] + bv.y);
        }
    }
    #undef K1_LOAD
}

// ======================= kernel 2: normalize -> fp16 half2 swizzled layout =======================
// Wg/Wv: word(kp, h) = m*8192 + kp*256 + (h ^ ((kp&3)<<3)), kp = d/2, value = half2(w[2kp][h], w[2kp+1][h])
// fc2  : word(hp, d) = 16384 + hp*64 + (d ^ ((hp&3)<<3)),  hp = h/2, value = half2(f[2hp][d], f[2hp+1][d])
__global__ __launch_bounds__(256) void k2_normalize() {
    __shared__ float sinv[256];
    __shared__ float part[4][64];
    const int b = blockIdx.x, tid = threadIdx.x;
    const float* P = g_params + (size_t)b * TOT;
    uint32_t* dst = g_wT + (size_t)b * WPB;

    #pragma unroll
    for (int m = 0; m < 2; m++) {
        const float* src = P + m * 16384;
        {
            float ss = 0.f;
            #pragma unroll 8
            for (int d = 0; d < 64; d++) { float v = src[d * 256 + tid]; ss += v * v; }
            sinv[tid] = 1.f / fmaxf(sqrtf(ss), 1e-12f);
        }
        __syncthreads();
        for (int idx = tid; idx < 8192; idx += 256) {
            int kp = idx >> 8, h = idx & 255;
            float inv = sinv[h];
            float a = src[(2 * kp) * 256 + h] * inv;
            float c = src[(2 * kp + 1) * 256 + h] * inv;
            dst[m * 8192 + kp * 256 + (h ^ ((kp & 3) << 3))] = pack2(a, c);
        }
        __syncthreads();
    }
    {
        const float* src = P + 32768;
        int q = tid >> 6, dd = tid & 63;
        float ss = 0.f;
        #pragma unroll 8
        for (int h = q * 64; h < q * 64 + 64; h++) { float v = src[h * 64 + dd]; ss += v * v; }
        part[q][dd] = ss;
        __syncthreads();
        if (tid < 64)
            sinv[tid] = 1.f / fmaxf(sqrtf(part[0][tid] + part[1][tid] + part[2][tid] + part[3][tid]), 1e-12f);
        __syncthreads();
        for (int idx = tid; idx < 8192; idx += 256) {
            int hp = idx >> 6, d = idx & 63;
            float inv = sinv[d];
            float a = src[(2 * hp) * 64 + d] * inv;
            float c = src[(2 * hp + 1) * 64 + d] * inv;
            dst[16384 + hp * 64 + (d ^ ((hp & 3) << 3))] = pack2(a, c);
        }
    }
}

// ======================= kernel 3: mma.sync fp16 fused MLP, 8 warps =======================
// grid (8, 64): 512 rows per CTA, 8 groups of 64 rows.
// 8 warps: hw = w>>2 (H half of 128), mw = w&3 (16-row m-tile).
// smem: 24576 words weights (96KB) | xn 64x36 half2 words (9KB) | out scratch [64][132] fp32 (33KB)
#define K3_SMEM ((24576 + 2304) * 4 + 8448 * 4)   // 141312 B

__global__ __launch_bounds__(256, 1) void k3_main(const float* __restrict__ x,
                                                  const float* __restrict__ scale,
                                                  float* __restrict__ out) {
    extern __shared__ uint32_t su[];
    uint32_t* xnw = su + 24576;              // [64][36] half2 words
    float* hs = (float*)(su + 26880);        // [64][132] fp32
    const int tid = threadIdx.x, w = tid >> 5, lane = tid & 31;
    const int b = blockIdx.y;
    const int hw = w >> 2, mw = w & 3, m0 = mw * 16;
    const int r = lane >> 2, q = lane & 3, q8 = q << 3;
    const int hoff = hw * 68;

    // preload weights (fp16 half2, swizzled): 6144 float4
    {
        const float4* wsrc = (const float4*)(g_wT + (size_t)b * WPB);
        float4* wdst = (float4*)su;
        #pragma unroll 8
        for (int i = tid; i < 6144; i += 256) wdst[i] = wsrc[i];
    }
    const int srow = tid >> 2, sqc = (tid & 3) * 16;
    float4 sc4[4];
    #pragma unroll
    for (int i = 0; i < 4; i++) sc4[i] = *(const float4*)(scale + sqc + 4 * i);
    __syncthreads();

    const uint32_t* Wg = su;
    const uint32_t* Wv = su + 8192;
    const uint32_t* Wf = su + 16384;

    for (int g = 0; g < 8; g++) {
        const int row0 = blockIdx.x * 512 + g * 64;

        // ---- stage RMSNorm'd xn (fp16 RNE, half2-packed) ----
        {
            const float4* xr = (const float4*)(x + ((size_t)b * NN + row0 + srow) * DD + sqc);
            float4 v[4];
            float ssq = 0.f;
            #pragma unroll
            for (int i = 0; i < 4; i++) {
                v[i] = xr[i];
                ssq += v[i].x * v[i].x + v[i].y * v[i].y + v[i].z * v[i].z + v[i].w * v[i].w;
            }
            ssq += __shfl_xor_sync(0xffffffffu, ssq, 1);
            ssq += __shfl_xor_sync(0xffffffffu, ssq, 2);
            const float rr = rsqrtf(ssq * (1.0f / 64.0f) + 1e-6f);
            uint32_t* xd = xnw + srow * 36 + (tid & 3) * 8;
            #pragma unroll
            for (int i = 0; i < 4; i++) {
                xd[2 * i]     = pack2(v[i].x * rr * sc4[i].x, v[i].y * rr * sc4[i].y);
                xd[2 * i + 1] = pack2(v[i].z * rr * sc4[i].z, v[i].w * rr * sc4[i].w);
            }
        }
        __syncthreads();

        float oacc[8][4];
        #pragma unroll
        for (int i = 0; i < 8; i++) { oacc[i][0] = oacc[i][1] = oacc[i][2] = oacc[i][3] = 0.f; }

        #pragma unroll
        for (int ch = 0; ch < 2; ch++) {
            const int nb = hw * 128 + ch * 64;

            // ---- MMA1: gate/value [16 x 64] over k=64 (4 x k16) ----
            float ga[8][4], va[8][4];
            #pragma unroll
            for (int i = 0; i < 8; i++) {
                ga[i][0] = ga[i][1] = ga[i][2] = ga[i][3] = 0.f;
                va[i][0] = va[i][1] = va[i][2] = va[i][3] = 0.f;
            }
            #pragma unroll
            for (int kt = 0; kt < 4; kt++) {
                uint32_t xa[4];
                const uint32_t* xb = xnw + (m0 + r) * 36 + kt * 8 + q;
                xa[0] = xb[0];
                xa[1] = xb[8 * 36];
                xa[2] = xb[4];
                xa[3] = xb[8 * 36 + 4];
                const uint32_t* g0 = Wg + (kt * 8 + q) * 256;
                const uint32_t* g1 = Wg + (kt * 8 + q + 4) * 256;
                const uint32_t* v0 = Wv + (kt * 8 + q) * 256;
                const uint32_t* v1 = Wv + (kt * 8 + q + 4) * 256;
                #pragma unroll
                for (int nt = 0; nt < 8; nt++) {
                    const int c = ((nb + nt * 8) ^ q8) + r;
                    mma_f16(ga[nt], xa, g0[c], g1[c]);
                    mma_f16(va[nt], xa, v0[c], v1[c]);
                }
            }

            // ---- silu*value in regs; acc layout == A layout (f16 k16) -> MMA2 directly ----
            #pragma unroll
            for (int kt2 = 0; kt2 < 4; kt2++) {
                const int t0 = 2 * kt2, t1 = 2 * kt2 + 1;
                float h00 = 0.5f * ga[t0][0] * (1.f + tanha(0.5f * ga[t0][0])) * va[t0][0];
                float h01 = 0.5f * ga[t0][1] * (1.f + tanha(0.5f * ga[t0][1])) * va[t0][1];
                float h02 = 0.5f * ga[t0][2] * (1.f + tanha(0.5f * ga[t0][2])) * va[t0][2];
                float h03 = 0.5f * ga[t0][3] * (1.f + tanha(0.5f * ga[t0][3])) * va[t0][3];
                float h10 = 0.5f * ga[t1][0] * (1.f + tanha(0.5f * ga[t1][0])) * va[t1][0];
                float h11 = 0.5f * ga[t1][1] * (1.f + tanha(0.5f * ga[t1][1])) * va[t1][1];
                float h12 = 0.5f * ga[t1][2] * (1.f + tanha(0.5f * ga[t1][2])) * va[t1][2];
                float h13 = 0.5f * ga[t1][3] * (1.f + tanha(0.5f * ga[t1][3])) * va[t1][3];
                uint32_t ha[4];
                ha[0] = pack2(h00, h01);   // (r,   k=2q,2q+1)  of block kt2
                ha[1] = pack2(h02, h03);   // (r+8, k=2q,2q+1)
                ha[2] = pack2(h10, h11);   // (r,   k=2q+8,2q+9)
                ha[3] = pack2(h12, h13);   // (r+8, k=2q+8,2q+9)
                const int hp0 = (nb >> 1) + kt2 * 8;
                const uint32_t* f0 = Wf + (hp0 + q) * 64;
                const uint32_t* f1 = Wf + (hp0 + q + 4) * 64;
                #pragma unroll
                for (int dt = 0; dt < 8; dt++) {
                    const int c = ((dt * 8) ^ q8) + r;
                    mma_f16(oacc[dt], ha, f0[c], f1[c]);
                }
            }
        }

        // ---- stash out partials (each warp owns rows m0..m0+15 x cols hoff..hoff+63) ----
        #pragma unroll
        for (int dt = 0; dt < 8; dt++) {
            *(float2*)&hs[(m0 + r) * 132 + hoff + dt * 8 + 2 * q]     = make_float2(oacc[dt][0], oacc[dt][1]);
            *(float2*)&hs[(m0 + r + 8) * 132 + hoff + dt * 8 + 2 * q] = make_float2(oacc[dt][2], oacc[dt][3]);
        }
        __syncthreads();

        // ---- reduce halves + residual + store ----
        {
            const float4* xr = (const float4*)(x + ((size_t)b * NN + row0 + srow) * DD + sqc);
            float* orow = out + ((size_t)b * NN + row0 + srow) * DD + sqc;
            #pragma unroll
            for (int i = 0; i < 4; i++) {
                float4 a  = *(const float4*)&hs[srow * 132 + sqc + 4 * i];
                float4 c  = *(const float4*)&hs[srow * 132 + 68 + sqc + 4 * i];
                float4 xv = xr[i];
                *(float4*)(orow + 4 * i) = make_float4(a.x + c.x + xv.x, a.y + c.y + xv.y,
                                                       a.z + c.z + xv.z, a.w + c.w + xv.w);
            }
        }
        __syncthreads();
    }
}

// ======================= launch =======================
extern "C" void kernel_launch(void* const* d_in, const int* in_sizes, int n_in,
                              void* d_out, int out_size) {
    const float* x     = (const float*)d_in[0];
    const float* s     = (const float*)d_in[1];
    const float* W     = (const float*)d_in[2];
    const float* bias  = (const float*)d_in[3];
    const float* scale = (const float*)d_in[4];
    float* out = (float*)d_out;

    cudaFuncSetAttribute(k1_mma, cudaFuncAttributeMaxDynamicSharedMemorySize, K1_SMEM);
    k1_mma<<<dim3(TOT / 128), 256, K1_SMEM>>>(s, W, bias);

    k2_normalize<<<dim3(BB), 256>>>();

    cudaFuncSetAttribute(k3_main, cudaFuncAttributeMaxDynamicSharedMemorySize, K3_SMEM);
    k3_main<<<dim3(8, BB), 256, K3_SMEM>>>(x, scale, out);
}

// round 8
// speedup vs baseline: 1.6255x; 1.0659x over previous
#include <cuda_runtime.h>
#include <cuda_fp16.h>
#include <cstdint>
#include <math.h>

#define BB   64
#define NN   4096
#define DD   64
#define HH   256
#define SS   1024
#define TOT  49152   // 3 * D * H
#define WPB  24576   // half2 words per batch (3*D*H/2)

// raw hypernet output (k1 -> k2)
__device__ float g_params[BB * (size_t)TOT];
// normalized fp16 weights, half2-packed along k, XOR-swizzled (k2 -> k3)
__device__ uint32_t g_wT[BB * (size_t)WPB];

// ======================= helpers =======================
__device__ __forceinline__ float tanha(float x) {
    float y;
    asm("tanh.approx.f32 %0, %1;" : "=f"(y) : "f"(x));
    return y;
}
__device__ __forceinline__ uint32_t pack2(float lo, float hi) {
    __half2 h = __floats2half2_rn(lo, hi);
    return *(uint32_t*)&h;
}
__device__ __forceinline__ uint32_t smem_u32(const void* p) {
    uint32_t a;
    asm("{ .reg .u64 t; cvta.to.shared.u64 t, %1; cvt.u32.u64 %0, t; }" : "=r"(a) : "l"(p));
    return a;
}
__device__ __forceinline__ void cpa16(uint32_t dst, const void* src) {
    asm volatile("cp.async.cg.shared.global [%0], [%1], 16;" :: "r"(dst), "l"(src));
}
#define CP_COMMIT() asm volatile("cp.async.commit_group;" ::: "memory")
#define CP_WAIT0()  asm volatile("cp.async.wait_group 0;" ::: "memory")
#define CP_WAIT2()  asm volatile("cp.async.wait_group 2;" ::: "memory")

// D += A * B  (m16n8k8, tf32 inputs, fp32 accum) — kernel 1
__device__ __forceinline__ void mma_tf32(float* d, const uint32_t* a, uint32_t b0, uint32_t b1) {
    asm volatile("mma.sync.aligned.m16n8k8.row.col.f32.tf32.tf32.f32 "
                 "{%0,%1,%2,%3}, {%4,%5,%6,%7}, {%8,%9}, {%0,%1,%2,%3};"
                 : "+f"(d[0]), "+f"(d[1]), "+f"(d[2]), "+f"(d[3])
                 : "r"(a[0]), "r"(a[1]), "r"(a[2]), "r"(a[3]), "r"(b0), "r"(b1));
}
// D += A * B  (m16n8k16, fp16 inputs, fp32 accum) — kernel 3
__device__ __forceinline__ void mma_f16(float* d, const uint32_t* a, uint32_t b0, uint32_t b1) {
    asm volatile("mma.sync.aligned.m16n8k16.row.col.f32.f16.f16.f32 "
                 "{%0,%1,%2,%3}, {%4,%5,%6,%7}, {%8,%9}, {%0,%1,%2,%3};"
                 : "+f"(d[0]), "+f"(d[1]), "+f"(d[2]), "+f"(d[3])
                 : "r"(a[0]), "r"(a[1]), "r"(a[2]), "r"(a[3]), "r"(b0), "r"(b1));
}

// ======================= kernel 1: hypernet GEMM, tf32 mma, 4-stage cp.async =======================
#define K1_STG_W (64 * 36 + 32 * 136)              // 6656 floats per stage
#define K1_SMEM  (4 * K1_STG_W * 4)                // 106496 B

__global__ __launch_bounds__(256) void k1_mma(const float* __restrict__ s,
                                              const float* __restrict__ W,
                                              const float* __restrict__ bias) {
    extern __shared__ float sk[];
    const int n0  = blockIdx.x * 128;
    const int tid = threadIdx.x;
    const int w = tid >> 5, lane = tid & 31;
    const int r = lane >> 2, q = lane & 3;
    const int m0 = (w & 1) * 32, nw = (w >> 1) * 32;
    const uint32_t sb = smem_u32(sk);

    #define K1_LOAD(st, k0) do {                                                   \
        _Pragma("unroll")                                                          \
        for (int i = 0; i < 2; i++) {                                              \
            int c = tid + i * 256;                                                 \
            int row = c >> 3, cc = c & 7;                                          \
            cpa16(sb + (uint32_t)((st) * K1_STG_W + row * 36 + cc * 4) * 4,        \
                  s + (size_t)row * SS + (k0) + cc * 4);                           \
        }                                                                          \
        _Pragma("unroll")                                                          \
        for (int i = 0; i < 4; i++) {                                              \
            int c = tid + i * 256;                                                 \
            int row = c >> 5, cc = c & 31;                                         \
            cpa16(sb + (uint32_t)((st) * K1_STG_W + 2304 + row * 136 + cc * 4) * 4,\
                  W + (size_t)((k0) + row) * TOT + n0 + cc * 4);                   \
        }                                                                          \
    } while (0)

    float acc[2][4][4];
    #pragma unroll
    for (int mf = 0; mf < 2; mf++)
        #pragma unroll
        for (int nf = 0; nf < 4; nf++)
            acc[mf][nf][0] = acc[mf][nf][1] = acc[mf][nf][2] = acc[mf][nf][3] = 0.f;

    K1_LOAD(0, 0);  CP_COMMIT();
    K1_LOAD(1, 32); CP_COMMIT();
    K1_LOAD(2, 64); CP_COMMIT();

    for (int ks = 0; ks < 32; ks++) {
        CP_WAIT2();
        __syncthreads();
        const int st = ks & 3;
        const float* A  = sk + st * K1_STG_W;
        const float* Bp = A + 2304;
        #pragma unroll
        for (int kk = 0; kk < 4; kk++) {
            uint32_t a[2][4];
            #pragma unroll
            for (int mf = 0; mf < 2; mf++) {
                const int mr = m0 + mf * 16 + r;
                a[mf][0] = __float_as_uint(A[mr * 36 + kk * 8 + q]);
                a[mf][1] = __float_as_uint(A[(mr + 8) * 36 + kk * 8 + q]);
                a[mf][2] = __float_as_uint(A[mr * 36 + kk * 8 + q + 4]);
                a[mf][3] = __float_as_uint(A[(mr + 8) * 36 + kk * 8 + q + 4]);
            }
            #pragma unroll
            for (int nf = 0; nf < 4; nf++) {
                const int cb = nw + nf * 8 + r;
                uint32_t b0 = __float_as_uint(Bp[(kk * 8 + q) * 136 + cb]);
                uint32_t b1 = __float_as_uint(Bp[(kk * 8 + q + 4) * 136 + cb]);
                mma_tf32(acc[0][nf], a[0], b0, b1);
                mma_tf32(acc[1][nf], a[1], b0, b1);
            }
        }
        __syncthreads();
        const int kn = (ks + 3) * 32;
        if (kn < SS) { K1_LOAD((ks + 3) & 3, kn); }
        CP_COMMIT();
    }

    #pragma unroll
    for (int nf = 0; nf < 4; nf++) {
        float2 bv = *(const float2*)(bias + n0 + nw + nf * 8 + 2 * q);
        #pragma unroll
        for (int mf = 0; mf < 2; mf++) {
            const int mr = m0 + mf * 16 + r;
            float* o0 = g_params + (size_t)mr * TOT + n0 + nw + nf * 8 + 2 * q;
            *(float2*)o0 = make_float2(acc[mf][nf][0] + bv.x, acc[mf][nf][1] + bv.y);
            float* o1 = g_params + (size_t)(mr + 8) * TOT + n0 + nw + nf * 8 + 2 * q;
            *(float2*)o1 = make_float2(acc[mf][nf][2] + bv.x, acc[mf][nf][3] + bv.y);
        }
    }
    #undef K1_LOAD
}

// ======================= kernel 2: normalize -> fp16 half2 swizzled layout =======================
__global__ __launch_bounds__(256) void k2_normalize() {
    __shared__ float sinv[256];
    __shared__ float part[4][64];
    const int b = blockIdx.x, tid = threadIdx.x;
    const float* P = g_params + (size_t)b * TOT;
    uint32_t* dst = g_wT + (size_t)b * WPB;

    #pragma unroll
    for (int m = 0; m < 2; m++) {
        const float* src = P + m * 16384;
        {
            float ss = 0.f;
            #pragma unroll 8
            for (int d = 0; d < 64; d++) { float v = src[d * 256 + tid]; ss += v * v; }
            sinv[tid] = 1.f / fmaxf(sqrtf(ss), 1e-12f);
        }
        __syncthreads();
        for (int idx = tid; idx < 8192; idx += 256) {
            int kp = idx >> 8, h = idx & 255;
            float inv = sinv[h];
            float a = src[(2 * kp) * 256 + h] * inv;
            float c = src[(2 * kp + 1) * 256 + h] * inv;
            dst[m * 8192 + kp * 256 + (h ^ ((kp & 3) << 3))] = pack2(a, c);
        }
        __syncthreads();
    }
    {
        const float* src = P + 32768;
        int q = tid >> 6, dd = tid & 63;
        float ss = 0.f;
        #pragma unroll 8
        for (int h = q * 64; h < q * 64 + 64; h++) { float v = src[h * 64 + dd]; ss += v * v; }
        part[q][dd] = ss;
        __syncthreads();
        if (tid < 64)
            sinv[tid] = 1.f / fmaxf(sqrtf(part[0][tid] + part[1][tid] + part[2][tid] + part[3][tid]), 1e-12f);
        __syncthreads();
        for (int idx = tid; idx < 8192; idx += 256) {
            int hp = idx >> 6, d = idx & 63;
            float inv = sinv[d];
            float a = src[(2 * hp) * 64 + d] * inv;
            float c = src[(2 * hp + 1) * 64 + d] * inv;
            dst[16384 + hp * 64 + (d ^ ((hp & 3) << 3))] = pack2(a, c);
        }
    }
}

// ======================= kernel 3: fp16 mma fused MLP, 1024 CTAs x 4 groups =======================
#define K3_SMEM ((24576 + 2304) * 4 + 8448 * 4)   // 141312 B

__global__ __launch_bounds__(256, 1) void k3_main(const float* __restrict__ x,
                                                  const float* __restrict__ scale,
                                                  float* __restrict__ out) {
    extern __shared__ uint32_t su[];
    uint32_t* xnw = su + 24576;              // [64][36] half2 words
    float* hs = (float*)(su + 26880);        // [64][132] fp32
    const int tid = threadIdx.x, w = tid >> 5, lane = tid & 31;
    const int b = blockIdx.x >> 4;           // 16 CTAs per batch
    const int gbase = (blockIdx.x & 15) * 4; // 4 groups of 64 rows per CTA
    const int hw = w >> 2, mw = w & 3, m0 = mw * 16;
    const int r = lane >> 2, q = lane & 3, q8 = q << 3;
    const int hoff = hw * 68;
    const uint32_t sb = smem_u32(su);

    // prefetch weights via cp.async (overlaps with group-0 RMS staging)
    {
        const uint32_t* wsrc = g_wT + (size_t)b * WPB;
        #pragma unroll 6
        for (int i = tid; i < 6144; i += 256)
            cpa16(sb + (uint32_t)i * 16, wsrc + i * 4);
        CP_COMMIT();
    }
    const int srow = tid >> 2, sqc = (tid & 3) * 16;
    float4 sc4[4];
    #pragma unroll
    for (int i = 0; i < 4; i++) sc4[i] = *(const float4*)(scale + sqc + 4 * i);

    const uint32_t* Wg = su;
    const uint32_t* Wv = su + 8192;
    const uint32_t* Wf = su + 16384;

    for (int g = 0; g < 4; g++) {
        const int row0 = (gbase + g) * 64;

        // ---- stage RMSNorm'd xn (fp16 RNE, half2-packed); keep residual in regs ----
        float4 xres[4];
        {
            const float4* xr = (const float4*)(x + ((size_t)b * NN + row0 + srow) * DD + sqc);
            float ssq = 0.f;
            #pragma unroll
            for (int i = 0; i < 4; i++) {
                xres[i] = xr[i];
                ssq += xres[i].x * xres[i].x + xres[i].y * xres[i].y
                     + xres[i].z * xres[i].z + xres[i].w * xres[i].w;
            }
            ssq += __shfl_xor_sync(0xffffffffu, ssq, 1);
            ssq += __shfl_xor_sync(0xffffffffu, ssq, 2);
            const float rr = rsqrtf(ssq * (1.0f / 64.0f) + 1e-6f);
            uint32_t* xd = xnw + srow * 36 + (tid & 3) * 8;
            #pragma unroll
            for (int i = 0; i < 4; i++) {
                xd[2 * i]     = pack2(xres[i].x * rr * sc4[i].x, xres[i].y * rr * sc4[i].y);
                xd[2 * i + 1] = pack2(xres[i].z * rr * sc4[i].z, xres[i].w * rr * sc4[i].w);
            }
        }
        if (g == 0) { CP_WAIT0(); }   // weights resident from here on
        __syncthreads();

        float oacc[8][4];
        #pragma unroll
        for (int i = 0; i < 8; i++) { oacc[i][0] = oacc[i][1] = oacc[i][2] = oacc[i][3] = 0.f; }

        #pragma unroll
        for (int ch = 0; ch < 2; ch++) {
            const int nb = hw * 128 + ch * 64;

            // ---- MMA1: gate/value [16 x 64] over k=64 (4 x k16) ----
            float ga[8][4], va[8][4];
            #pragma unroll
            for (int i = 0; i < 8; i++) {
                ga[i][0] = ga[i][1] = ga[i][2] = ga[i][3] = 0.f;
                va[i][0] = va[i][1] = va[i][2] = va[i][3] = 0.f;
            }
            #pragma unroll
            for (int kt = 0; kt < 4; kt++) {
                uint32_t xa[4];
                const uint32_t* xb = xnw + (m0 + r) * 36 + kt * 8 + q;
                xa[0] = xb[0];
                xa[1] = xb[8 * 36];
                xa[2] = xb[4];
                xa[3] = xb[8 * 36 + 4];
                const uint32_t* g0 = Wg + (kt * 8 + q) * 256;
                const uint32_t* g1 = Wg + (kt * 8 + q + 4) * 256;
                const uint32_t* v0 = Wv + (kt * 8 + q) * 256;
                const uint32_t* v1 = Wv + (kt * 8 + q + 4) * 256;
                #pragma unroll
                for (int nt = 0; nt < 8; nt++) {
                    const int c = ((nb + nt * 8) ^ q8) + r;
                    mma_f16(ga[nt], xa, g0[c], g1[c]);
                    mma_f16(va[nt], xa, v0[c], v1[c]);
                }
            }

            // ---- silu*value in regs; acc layout == A layout (f16 k16) -> MMA2 directly ----
            #pragma unroll
            for (int kt2 = 0; kt2 < 4; kt2++) {
                const int t0 = 2 * kt2, t1 = 2 * kt2 + 1;
                float h00 = 0.5f * ga[t0][0] * (1.f + tanha(0.5f * ga[t0][0])) * va[t0][0];
                float h01 = 0.5f * ga[t0][1] * (1.f + tanha(0.5f * ga[t0][1])) * va[t0][1];
                float h02 = 0.5f * ga[t0][2] * (1.f + tanha(0.5f * ga[t0][2])) * va[t0][2];
                float h03 = 0.5f * ga[t0][3] * (1.f + tanha(0.5f * ga[t0][3])) * va[t0][3];
                float h10 = 0.5f * ga[t1][0] * (1.f + tanha(0.5f * ga[t1][0])) * va[t1][0];
                float h11 = 0.5f * ga[t1][1] * (1.f + tanha(0.5f * ga[t1][1])) * va[t1][1];
                float h12 = 0.5f * ga[t1][2] * (1.f + tanha(0.5f * ga[t1][2])) * va[t1][2];
                float h13 = 0.5f * ga[t1][3] * (1.f + tanha(0.5f * ga[t1][3])) * va[t1][3];
                uint32_t ha[4];
                ha[0] = pack2(h00, h01);
                ha[1] = pack2(h02, h03);
                ha[2] = pack2(h10, h11);
                ha[3] = pack2(h12, h13);
                const int hp0 = (nb >> 1) + kt2 * 8;
                const uint32_t* f0 = Wf + (hp0 + q) * 64;
                const uint32_t* f1 = Wf + (hp0 + q + 4) * 64;
                #pragma unroll
                for (int dt = 0; dt < 8; dt++) {
                    const int c = ((dt * 8) ^ q8) + r;
                    mma_f16(oacc[dt], ha, f0[c], f1[c]);
                }
            }
        }

        // ---- stash out partials ----
        #pragma unroll
        for (int dt = 0; dt < 8; dt++) {
            *(float2*)&hs[(m0 + r) * 132 + hoff + dt * 8 + 2 * q]     = make_float2(oacc[dt][0], oacc[dt][1]);
            *(float2*)&hs[(m0 + r + 8) * 132 + hoff + dt * 8 + 2 * q] = make_float2(oacc[dt][2], oacc[dt][3]);
        }
        __syncthreads();

        // ---- reduce halves + residual (regs) + store ----
        {
            float* orow = out + ((size_t)b * NN + row0 + srow) * DD + sqc;
            #pragma unroll
            for (int i = 0; i < 4; i++) {
                float4 a = *(const float4*)&hs[srow * 132 + sqc + 4 * i];
                float4 c = *(const float4*)&hs[srow * 132 + 68 + sqc + 4 * i];
                *(float4*)(orow + 4 * i) = make_float4(a.x + c.x + xres[i].x, a.y + c.y + xres[i].y,
                                                       a.z + c.z + xres[i].z, a.w + c.w + xres[i].w);
            }
        }
        __syncthreads();
    }
}

// ======================= launch =======================
extern "C" void kernel_launch(void* const* d_in, const int* in_sizes, int n_in,
                              void* d_out, int out_size) {
    const float* x     = (const float*)d_in[0];
    const float* s     = (const float*)d_in[1];
    const float* W     = (const float*)d_in[2];
    const float* bias  = (const float*)d_in[3];
    const float* scale = (const float*)d_in[4];
    float* out = (float*)d_out;

    cudaFuncSetAttribute(k1_mma, cudaFuncAttributeMaxDynamicSharedMemorySize, K1_SMEM);
    k1_mma<<<dim3(TOT / 128), 256, K1_SMEM>>>(s, W, bias);

    k2_normalize<<<dim3(BB), 256>>>();

    cudaFuncSetAttribute(k3_main, cudaFuncAttributeMaxDynamicSharedMemorySize, K3_SMEM);
    k3_main<<<dim3(1024), 256, K3_SMEM>>>(x, scale, out);
}